// round 6
// baseline (speedup 1.0000x reference)
#include <cuda_runtime.h>
#include <math.h>

// Problem constants
#define BB 4
#define SS 2048
#define DD 1024
#define HH 16
#define DH 64
#define NT (BB*SS)          // 8192 tokens
#define SCALE_F 0.125f      // 64^-0.5

// Scratch (device globals: allocation-free rule)
__device__ float g_Q[(size_t)BB*HH*SS*DH];   // [B,H,S,Dh]
__device__ float g_K[(size_t)BB*HH*SS*DH];
__device__ float g_V[(size_t)BB*HH*SS*DH];
__device__ float g_O[(size_t)NT*DD];         // [B,S,D], RNA-tf32 rounded
__device__ float g_X[(size_t)NT*DD];         // RNA-tf32 rounded x
__device__ float g_W4[(size_t)4*DD*DD];      // RNA-tf32 rounded weights [K,N]

// ---------------------------------------------------------------------------
// helpers
// ---------------------------------------------------------------------------
__device__ __forceinline__ unsigned f2tf(float x) {
    unsigned u;
    asm("cvt.rna.tf32.f32 %0, %1;" : "=r"(u) : "f"(x));
    return u;
}

__device__ __forceinline__ void mma_tf32(float* c, const unsigned* a, const unsigned* b) {
    asm volatile(
        "mma.sync.aligned.m16n8k8.row.col.f32.tf32.tf32.f32 "
        "{%0,%1,%2,%3}, {%4,%5,%6,%7}, {%8,%9}, {%0,%1,%2,%3};\n"
        : "+f"(c[0]), "+f"(c[1]), "+f"(c[2]), "+f"(c[3])
        : "r"(a[0]), "r"(a[1]), "r"(a[2]), "r"(a[3]),
          "r"(b[0]), "r"(b[1]));
}

__device__ __forceinline__ void cp_async16(unsigned smem_addr, const void* gptr) {
    asm volatile("cp.async.ca.shared.global [%0], [%1], 16;\n"
                 :: "r"(smem_addr), "l"(gptr));
}
__device__ __forceinline__ void cp_commit() {
    asm volatile("cp.async.commit_group;\n" ::: "memory");
}
template<int N>
__device__ __forceinline__ void cp_wait() {
    asm volatile("cp.async.wait_group %0;\n" :: "n"(N) : "memory");
}

// ---------------------------------------------------------------------------
// Pre-pass: RNA-tf32 rounding (elementwise, float4)
// ---------------------------------------------------------------------------
__global__ __launch_bounds__(256) void cvt_rna(const float* __restrict__ src,
                                               float* __restrict__ dst)
{
    const size_t i = (size_t)(blockIdx.x * 256 + threadIdx.x) * 4;
    float4 v = *(const float4*)&src[i];
    float4 o;
    o.x = __uint_as_float(f2tf(v.x));
    o.y = __uint_as_float(f2tf(v.y));
    o.z = __uint_as_float(f2tf(v.z));
    o.w = __uint_as_float(f2tf(v.w));
    *(float4*)&dst[i] = o;
}

// ---------------------------------------------------------------------------
// TF32 GEMM v3 (fixed pipeline): 128x128x32 tiles, 256 threads (8 warps,
// warp tile 32x64), pre-converted inputs, bare cp.async double buffering.
//  A smem: [m][k] stride 36 ; B smem: [k][n] stride 136
// amode: 0 -> A = g_X, 1 -> A = g_O
// omode: 0/1/2 -> [B,H,S,Dh] into g_Q/g_K/g_V ; 3 -> plain [M,N] to outp
// ---------------------------------------------------------------------------
#define G_ASTR 36
#define G_BSTR 136
#define G_ASZ (128*G_ASTR)   // floats
#define G_BSZ (32*G_BSTR)
#define G_SMEM (2*(G_ASZ + G_BSZ)*4)   // 71680 bytes

__global__ __launch_bounds__(256) void gemm_cp(
    const float* __restrict__ bias, float* __restrict__ outp,
    int amode, int omode, int widx)
{
    const float* A  = amode ? g_O : g_X;
    const float* Bw = g_W4 + (size_t)widx * DD * DD;
    float* out = (omode == 0) ? g_Q : (omode == 1) ? g_K : (omode == 2) ? g_V : outp;

    extern __shared__ unsigned smem_u[];
    unsigned* As = smem_u;               // [2][128][36]
    unsigned* Bs = smem_u + 2 * G_ASZ;   // [2][32][136]
    const unsigned asm_base = (unsigned)__cvta_generic_to_shared(As);
    const unsigned bsm_base = (unsigned)__cvta_generic_to_shared(Bs);

    const int bm = blockIdx.y * 128;
    const int bn = blockIdx.x * 128;
    const int tid = threadIdx.x;
    const int warp = tid >> 5, lane = tid & 31;
    const int g = lane >> 2, t = lane & 3;
    const int wm0 = (warp >> 1) * 32;
    const int wn0 = (warp & 1) * 64;

    // cp.async mapping: A chunk 128x32 -> 1024 segs (8/row); B chunk 32x128 -> 1024 segs (32/row)
    const int aseg = tid & 7;            // 16B col within A row
    const int bseg = tid & 31;           // 16B col within B row
    int arow[4], brow[4];
#pragma unroll
    for (int p = 0; p < 4; p++) {
        arow[p] = (tid + 256 * p) >> 3;
        brow[p] = (tid + 256 * p) >> 5;
    }
    const float* Abase = A + (size_t)bm * DD;

    auto load_chunk = [&](int kt, int buf) {
        const int k0 = kt * 32;
        const unsigned ab = asm_base + (unsigned)buf * G_ASZ * 4;
        const unsigned bb = bsm_base + (unsigned)buf * G_BSZ * 4;
#pragma unroll
        for (int p = 0; p < 4; p++) {
            cp_async16(ab + (unsigned)arow[p] * (G_ASTR * 4) + (unsigned)aseg * 16,
                       Abase + (size_t)arow[p] * DD + k0 + aseg * 4);
            cp_async16(bb + (unsigned)brow[p] * (G_BSTR * 4) + (unsigned)bseg * 16,
                       Bw + (size_t)(k0 + brow[p]) * DD + bn + bseg * 4);
        }
        cp_commit();
    };

    float acc[2][8][4];
#pragma unroll
    for (int mi = 0; mi < 2; mi++)
#pragma unroll
        for (int ni = 0; ni < 8; ni++)
#pragma unroll
            for (int q = 0; q < 4; q++) acc[mi][ni][q] = 0.f;

    load_chunk(0, 0);

    const int NKT = DD / 32;  // 32
    int buf = 0;
    for (int kt = 0; kt < NKT; kt++) {
        // FIX: commit prefetch of chunk kt+1 BEFORE the wait, so cp_wait<1>
        // retires the oldest pending group (= chunk kt, the one we consume).
        if (kt + 1 < NKT) {
            load_chunk(kt + 1, buf ^ 1);   // safe: prev iter's closing barrier
            cp_wait<1>();                  //   guarantees buf^1 reads are done
        } else {
            cp_wait<0>();
        }
        __syncthreads();

        const unsigned* Ab = As + buf * G_ASZ;
        const unsigned* Bb = Bs + buf * G_BSZ;
#pragma unroll
        for (int ks = 0; ks < 4; ks++) {
            const int k0 = ks * 8;
            unsigned a[2][4];
#pragma unroll
            for (int mi = 0; mi < 2; mi++) {
                const unsigned* ap = Ab + (wm0 + 16 * mi + g) * G_ASTR;
                a[mi][0] = ap[k0 + t];
                a[mi][1] = ap[8 * G_ASTR + k0 + t];
                a[mi][2] = ap[k0 + t + 4];
                a[mi][3] = ap[8 * G_ASTR + k0 + t + 4];
            }
            unsigned b[8][2];
#pragma unroll
            for (int ni = 0; ni < 8; ni++) {
                b[ni][0] = Bb[(k0 + t) * G_BSTR + wn0 + 8 * ni + g];
                b[ni][1] = Bb[(k0 + t + 4) * G_BSTR + wn0 + 8 * ni + g];
            }
#pragma unroll
            for (int mi = 0; mi < 2; mi++)
#pragma unroll
                for (int ni = 0; ni < 8; ni++)
                    mma_tf32(acc[mi][ni], a[mi], b[ni]);
        }
        __syncthreads();
        buf ^= 1;
    }

    // Epilogue: bias + layout
#pragma unroll
    for (int mi = 0; mi < 2; mi++) {
#pragma unroll
        for (int ni = 0; ni < 8; ni++) {
            const int c = bn + wn0 + 8 * ni + 2 * t;
            const float2 bb = *(const float2*)&bias[c];
#pragma unroll
            for (int hr = 0; hr < 2; hr++) {
                const int r = bm + wm0 + 16 * mi + g + 8 * hr;
                float2 v;
                v.x = acc[mi][ni][2 * hr + 0] + bb.x;
                v.y = acc[mi][ni][2 * hr + 1] + bb.y;
                if (omode < 3) {
                    const int b = r >> 11, srow = r & (SS - 1);
                    const int h = c >> 6, d = c & (DH - 1);
                    *(float2*)&out[(((size_t)b * HH + h) * SS + srow) * DH + d] = v;
                } else {
                    *(float2*)&out[(size_t)r * DD + c] = v;
                }
            }
        }
    }
}

// ---------------------------------------------------------------------------
// TF32 flash attention v3:
//  - CTA = 128 queries of one (b,h), 256 threads (8 warps x 16 q-rows, mi=1)
//  - Q fragments register-resident (staged through the P buffer)
//  - K/V double-buffered via cp.async; 2 CTAs/SM
//  - O written RNA-tf32-rounded for the final GEMM
// ---------------------------------------------------------------------------
#define A_KSTR 68
#define A_VSTR 72
#define A_PSTR 68
#define A_KSZ (64*A_KSTR)
#define A_VSZ (64*A_VSTR)
#define A_PSZ (128*A_PSTR)
#define A_SMEM ((A_PSZ + 2*A_KSZ + 2*A_VSZ)*4)   // 106496 bytes

__global__ __launch_bounds__(256, 2) void attn_tf32()
{
    extern __shared__ unsigned sm_u[];
    unsigned* Ps = sm_u;                 // [128][68], also Q staging
    unsigned* Ks = Ps + A_PSZ;           // [2][64][68]
    unsigned* Vs = Ks + 2 * A_KSZ;       // [2][64][72]

    const int qb = blockIdx.x;           // 0..15
    const int bh = blockIdx.y;           // 0..63
    const float* Qg = g_Q + (size_t)bh * SS * DH + (size_t)qb * 128 * DH;
    const float* Kg = g_K + (size_t)bh * SS * DH;
    const float* Vg = g_V + (size_t)bh * SS * DH;

    const int tid = threadIdx.x;
    const int warp = tid >> 5, lane = tid & 31;
    const int g = lane >> 2, t = lane & 3;
    const int m0 = warp * 16;            // warp's 16 query rows

    const unsigned ksm_base = (unsigned)__cvta_generic_to_shared(Ks);
    const unsigned vsm_base = (unsigned)__cvta_generic_to_shared(Vs);

    // cp.async mapping: one 64x64 chunk = 1024 16B segs / 256 thr = 4 each
    int cprow[4];
#pragma unroll
    for (int p = 0; p < 4; p++) cprow[p] = (tid + 256 * p) >> 4;
    const int cpc16 = tid & 15;

    // prologue: start chunk 0 load
#pragma unroll
    for (int p = 0; p < 4; p++) {
        cp_async16(ksm_base + (cprow[p] * A_KSTR + cpc16 * 4) * 4,
                   &Kg[(size_t)cprow[p] * DH + cpc16 * 4]);
        cp_async16(vsm_base + (cprow[p] * A_VSTR + cpc16 * 4) * 4,
                   &Vg[(size_t)cprow[p] * DH + cpc16 * 4]);
    }
    cp_commit();

    // stage Q (scaled, RNA) through Ps; extract fragments to registers
#pragma unroll
    for (int p = 0; p < 8; p++) {
        const int idx = tid + p * 256;
        const int row = idx >> 4, c4 = idx & 15;
        float4 v = *(const float4*)&Qg[(size_t)row * DH + c4 * 4];
        *(uint4*)&Ps[row * A_PSTR + c4 * 4] =
            make_uint4(f2tf(v.x * SCALE_F), f2tf(v.y * SCALE_F),
                       f2tf(v.z * SCALE_F), f2tf(v.w * SCALE_F));
    }
    __syncthreads();

    unsigned qf[8][4];
    {
        const unsigned* qp = Ps + (m0 + g) * A_PSTR;
#pragma unroll
        for (int ks = 0; ks < 8; ks++) {
            const int k0 = ks * 8;
            qf[ks][0] = qp[k0 + t];
            qf[ks][1] = qp[8 * A_PSTR + k0 + t];
            qf[ks][2] = qp[k0 + t + 4];
            qf[ks][3] = qp[8 * A_PSTR + k0 + t + 4];
        }
    }
    // From here, each warp only touches its own 16 Ps rows.

    float o[8][4];
#pragma unroll
    for (int ni = 0; ni < 8; ni++)
#pragma unroll
        for (int q = 0; q < 4; q++) o[ni][q] = 0.f;
    float mi0 = -1e30f, mi1 = -1e30f, li0 = 0.f, li1 = 0.f;

    const int NCH = SS / 64;  // 32
    for (int kt = 0; kt < NCH; kt++) {
        const int buf = kt & 1;
        if (kt + 1 < NCH) {
            const int kv1 = (kt + 1) * 64;
            const unsigned kb = ksm_base + (buf ^ 1) * A_KSZ * 4;
            const unsigned vb = vsm_base + (buf ^ 1) * A_VSZ * 4;
#pragma unroll
            for (int p = 0; p < 4; p++) {
                cp_async16(kb + (cprow[p] * A_KSTR + cpc16 * 4) * 4,
                           &Kg[(size_t)(kv1 + cprow[p]) * DH + cpc16 * 4]);
                cp_async16(vb + (cprow[p] * A_VSTR + cpc16 * 4) * 4,
                           &Vg[(size_t)(kv1 + cprow[p]) * DH + cpc16 * 4]);
            }
            cp_commit();
            cp_wait<1>();
        } else {
            cp_wait<0>();
        }
        __syncthreads();

        const unsigned* Kb = Ks + buf * A_KSZ;
        const unsigned* Vb = Vs + buf * A_VSZ;

        // S = Q K^T : warp computes 16x64
        float s[8][4];
#pragma unroll
        for (int ni = 0; ni < 8; ni++)
#pragma unroll
            for (int q = 0; q < 4; q++) s[ni][q] = 0.f;

#pragma unroll
        for (int ks = 0; ks < 8; ks++) {
            const int k0 = ks * 8;
#pragma unroll
            for (int ni = 0; ni < 8; ni++) {
                unsigned b[2];
                b[0] = Kb[(8 * ni + g) * A_KSTR + k0 + t];
                b[1] = Kb[(8 * ni + g) * A_KSTR + k0 + t + 4];
                mma_tf32(s[ni], qf[ks], b);
            }
        }

        // online softmax (rows r0 = m0+g, r1 = r0+8)
        float mx0 = -1e30f, mx1 = -1e30f;
#pragma unroll
        for (int ni = 0; ni < 8; ni++) {
            mx0 = fmaxf(mx0, fmaxf(s[ni][0], s[ni][1]));
            mx1 = fmaxf(mx1, fmaxf(s[ni][2], s[ni][3]));
        }
        mx0 = fmaxf(mx0, __shfl_xor_sync(0xffffffffu, mx0, 1));
        mx0 = fmaxf(mx0, __shfl_xor_sync(0xffffffffu, mx0, 2));
        mx1 = fmaxf(mx1, __shfl_xor_sync(0xffffffffu, mx1, 1));
        mx1 = fmaxf(mx1, __shfl_xor_sync(0xffffffffu, mx1, 2));

        const float mn0 = fmaxf(mi0, mx0), mn1 = fmaxf(mi1, mx1);
        const float corr0 = __expf(mi0 - mn0), corr1 = __expf(mi1 - mn1);
        mi0 = mn0; mi1 = mn1;

        float rs0 = 0.f, rs1 = 0.f;
        unsigned* pr0 = Ps + (m0 + g) * A_PSTR;
        unsigned* pr1 = pr0 + 8 * A_PSTR;
#pragma unroll
        for (int ni = 0; ni < 8; ni++) {
            const float p00 = __expf(s[ni][0] - mn0);
            const float p01 = __expf(s[ni][1] - mn0);
            const float p10 = __expf(s[ni][2] - mn1);
            const float p11 = __expf(s[ni][3] - mn1);
            rs0 += p00 + p01;
            rs1 += p10 + p11;
            *(uint2*)&pr0[8 * ni + 2 * t] = make_uint2(f2tf(p00), f2tf(p01));
            *(uint2*)&pr1[8 * ni + 2 * t] = make_uint2(f2tf(p10), f2tf(p11));
        }
        rs0 += __shfl_xor_sync(0xffffffffu, rs0, 1);
        rs0 += __shfl_xor_sync(0xffffffffu, rs0, 2);
        rs1 += __shfl_xor_sync(0xffffffffu, rs1, 1);
        rs1 += __shfl_xor_sync(0xffffffffu, rs1, 2);
        li0 = li0 * corr0 + rs0;
        li1 = li1 * corr1 + rs1;
#pragma unroll
        for (int ni = 0; ni < 8; ni++) {
            o[ni][0] *= corr0; o[ni][1] *= corr0;
            o[ni][2] *= corr1; o[ni][3] *= corr1;
        }
        __syncwarp();   // P rows are warp-private

        // O += P V : warp 16x64
#pragma unroll
        for (int ks = 0; ks < 8; ks++) {
            const int k0 = ks * 8;
            unsigned a[4];
            const unsigned* pp = Ps + (m0 + g) * A_PSTR;
            a[0] = pp[k0 + t];
            a[1] = pp[8 * A_PSTR + k0 + t];
            a[2] = pp[k0 + t + 4];
            a[3] = pp[8 * A_PSTR + k0 + t + 4];
#pragma unroll
            for (int ni = 0; ni < 8; ni++) {
                unsigned b[2];
                b[0] = Vb[(k0 + t) * A_VSTR + 8 * ni + g];
                b[1] = Vb[(k0 + t + 4) * A_VSTR + 8 * ni + g];
                mma_tf32(o[ni], a, b);
            }
        }
        __syncthreads();   // all warps done with buf before refill
    }

    // epilogue: normalize + RNA round, write g_O [B,S,D]
    const int b = bh >> 4, h = bh & 15;
    const float inv0 = 1.f / li0, inv1 = 1.f / li1;
    const int s0 = qb * 128 + m0 + g;
#pragma unroll
    for (int ni = 0; ni < 8; ni++) {
        const int col = h * DH + 8 * ni + 2 * t;
        *(float2*)&g_O[((size_t)b * SS + s0) * DD + col] =
            make_float2(__uint_as_float(f2tf(o[ni][0] * inv0)),
                        __uint_as_float(f2tf(o[ni][1] * inv0)));
        *(float2*)&g_O[((size_t)b * SS + s0 + 8) * DD + col] =
            make_float2(__uint_as_float(f2tf(o[ni][2] * inv1)),
                        __uint_as_float(f2tf(o[ni][3] * inv1)));
    }
}

// ---------------------------------------------------------------------------
extern "C" void kernel_launch(void* const* d_in, const int* in_sizes, int n_in,
                              void* d_out, int out_size)
{
    const float* x  = (const float*)d_in[0];
    const float* Wq = (const float*)d_in[1];
    const float* bq = (const float*)d_in[2];
    const float* Wk = (const float*)d_in[3];
    const float* bk = (const float*)d_in[4];
    const float* Wv = (const float*)d_in[5];
    const float* bv = (const float*)d_in[6];
    const float* Wo = (const float*)d_in[7];
    const float* bo = (const float*)d_in[8];
    float* out = (float*)d_out;

    static int configured = 0;
    if (!configured) {
        cudaFuncSetAttribute(gemm_cp, cudaFuncAttributeMaxDynamicSharedMemorySize, G_SMEM);
        cudaFuncSetAttribute(attn_tf32, cudaFuncAttributeMaxDynamicSharedMemorySize, A_SMEM);
        configured = 1;
    }

    // resolve device-global scratch addresses (host side, cached)
    static float *p_X = nullptr, *p_W4 = nullptr;
    if (!p_X) {
        cudaGetSymbolAddress((void**)&p_X, g_X);
        cudaGetSymbolAddress((void**)&p_W4, g_W4);
    }

    // pre-pass: RNA-tf32 rounding (x + 4 weights, no transpose needed)
    cvt_rna<<<(NT * DD) / 1024, 256>>>(x, p_X);
    cvt_rna<<<(DD * DD) / 1024, 256>>>(Wq, p_W4 + 0 * (size_t)DD * DD);
    cvt_rna<<<(DD * DD) / 1024, 256>>>(Wk, p_W4 + 1 * (size_t)DD * DD);
    cvt_rna<<<(DD * DD) / 1024, 256>>>(Wv, p_W4 + 2 * (size_t)DD * DD);
    cvt_rna<<<(DD * DD) / 1024, 256>>>(Wo, p_W4 + 3 * (size_t)DD * DD);

    dim3 gg(DD / 128, NT / 128);  // (8, 64)
    gemm_cp<<<gg, 256, G_SMEM>>>(bq, nullptr, 0, 0, 0);
    gemm_cp<<<gg, 256, G_SMEM>>>(bk, nullptr, 0, 1, 1);
    gemm_cp<<<gg, 256, G_SMEM>>>(bv, nullptr, 0, 2, 2);

    attn_tf32<<<dim3(SS / 128, BB * HH), 256, A_SMEM>>>();

    gemm_cp<<<gg, 256, G_SMEM>>>(bo, out, 1, 3, 3);
}

// round 7
// speedup vs baseline: 1.7361x; 1.7361x over previous
#include <cuda_runtime.h>
#include <math.h>

// Problem constants
#define BB 4
#define SS 2048
#define DD 1024
#define HH 16
#define DH 64
#define NT (BB*SS)          // 8192 tokens
#define SCALE_F 0.125f      // 64^-0.5

// Scratch (device globals; fp16 stored as u16)
__device__ unsigned short g_Qh[(size_t)BB*HH*SS*DH];  // [B,H,S,Dh], pre-scaled
__device__ unsigned short g_Kh[(size_t)BB*HH*SS*DH];  // [B,H,S,Dh]
__device__ unsigned short g_Vh[(size_t)BB*HH*DH*SS];  // [B,H,Dh,S]  (transposed!)
__device__ unsigned short g_Oh[(size_t)NT*DD];        // [B,S,D]
__device__ unsigned short g_Xh[(size_t)NT*DD];        // fp16 x
__device__ unsigned short g_Wh[(size_t)4*DD*DD];      // fp16 weights, [N][K]

// ---------------------------------------------------------------------------
// helpers
// ---------------------------------------------------------------------------
__device__ __forceinline__ unsigned pack_h2(float lo, float hi) {
    unsigned u;
    asm("cvt.rn.f16x2.f32 %0, %1, %2;" : "=r"(u) : "f"(hi), "f"(lo));
    return u;
}
__device__ __forceinline__ unsigned short f2h(float x) {
    unsigned short h;
    asm("cvt.rn.f16.f32 %0, %1;" : "=h"(h) : "f"(x));
    return h;
}

__device__ __forceinline__ void mma_f16(float* c, const unsigned* a, const unsigned* b) {
    asm volatile(
        "mma.sync.aligned.m16n8k16.row.col.f32.f16.f16.f32 "
        "{%0,%1,%2,%3}, {%4,%5,%6,%7}, {%8,%9}, {%0,%1,%2,%3};\n"
        : "+f"(c[0]), "+f"(c[1]), "+f"(c[2]), "+f"(c[3])
        : "r"(a[0]), "r"(a[1]), "r"(a[2]), "r"(a[3]),
          "r"(b[0]), "r"(b[1]));
}

__device__ __forceinline__ void cp_async16(unsigned smem_addr, const void* gptr) {
    asm volatile("cp.async.ca.shared.global [%0], [%1], 16;\n"
                 :: "r"(smem_addr), "l"(gptr));
}
__device__ __forceinline__ void cp_commit() {
    asm volatile("cp.async.commit_group;\n" ::: "memory");
}
template<int N>
__device__ __forceinline__ void cp_wait() {
    asm volatile("cp.async.wait_group %0;\n" :: "n"(N) : "memory");
}

// ---------------------------------------------------------------------------
// Pre-pass: x f32 -> fp16 ; weights f32 [K][N] -> fp16 [N][K]
// ---------------------------------------------------------------------------
__global__ __launch_bounds__(256) void cvt_xh(const float* __restrict__ x)
{
    const size_t i = (size_t)(blockIdx.x * 256 + threadIdx.x) * 8;
    float4 v0 = *(const float4*)&x[i];
    float4 v1 = *(const float4*)&x[i + 4];
    uint4 o;
    o.x = pack_h2(v0.x, v0.y);
    o.y = pack_h2(v0.z, v0.w);
    o.z = pack_h2(v1.x, v1.y);
    o.w = pack_h2(v1.z, v1.w);
    *(uint4*)&g_Xh[i] = o;
}

__global__ __launch_bounds__(256) void transpose_wh(const float* __restrict__ W, int widx)
{
    __shared__ float t[32][33];
    unsigned short* Wt = g_Wh + (size_t)widx * DD * DD;
    const int n0 = blockIdx.x * 32, k0 = blockIdx.y * 32;
    const int tx = threadIdx.x & 31, ty = threadIdx.x >> 5;   // 32x8
#pragma unroll
    for (int i = 0; i < 4; i++)
        t[ty + 8 * i][tx] = W[(size_t)(k0 + ty + 8 * i) * DD + n0 + tx];
    __syncthreads();
#pragma unroll
    for (int i = 0; i < 4; i++)
        Wt[(size_t)(n0 + ty + 8 * i) * DD + k0 + tx] = f2h(t[tx][ty + 8 * i]);
}

// ---------------------------------------------------------------------------
// FP16 GEMM: 128x128 tiles, K-chunks of 32, 256 threads (8 warps, warp 32x64),
// cp.async double-buffered, mma.m16n8k16.
//  A smem: [128][40] half ; B smem (weights [N][K]): [128][40] half
// amode: 0 -> A = g_Xh, 1 -> A = g_Oh
// omode: 0 Q (scaled, [B,H,S,Dh]) / 1 K / 2 V transposed [B,H,Dh,S] / 3 f32 out
// ---------------------------------------------------------------------------
#define GH_STR 40
#define GH_TILE (128*GH_STR)               // halfs per tensor per buffer
#define GH_SMEM (2*2*GH_TILE*2)            // 40960 bytes

__global__ __launch_bounds__(256, 2) void gemm_h(
    const float* __restrict__ bias, float* __restrict__ outp,
    int amode, int omode, int widx)
{
    const unsigned short* A  = amode ? g_Oh : g_Xh;
    const unsigned short* Bw = g_Wh + (size_t)widx * DD * DD;

    extern __shared__ unsigned short smem_h[];
    unsigned short* Ash = smem_h;                    // [2][128][40]
    unsigned short* Bsh = smem_h + 2 * GH_TILE;      // [2][128][40]
    const unsigned abase = (unsigned)__cvta_generic_to_shared(Ash);
    const unsigned bbase = (unsigned)__cvta_generic_to_shared(Bsh);

    const int bm = blockIdx.y * 128;
    const int bn = blockIdx.x * 128;
    const int tid = threadIdx.x;
    const int warp = tid >> 5, lane = tid & 31;
    const int g = lane >> 2, t = lane & 3;
    const int wm0 = (warp >> 1) * 32;
    const int wn0 = (warp & 1) * 64;

    // cp.async: chunk = 128 rows x 32 halfs (64B = 4 segs/row); 512 segs/tensor
    const int seg = tid & 3;                         // 16B (8 halfs) column
    int row0 = tid >> 2, row1 = row0 + 64;
    const unsigned short* Abase = A + (size_t)bm * DD;

    auto load_chunk = [&](int kt, int buf) {
        const int k0 = kt * 32 + seg * 8;
        const unsigned ab = abase + (unsigned)buf * GH_TILE * 2;
        const unsigned bb = bbase + (unsigned)buf * GH_TILE * 2;
        cp_async16(ab + (unsigned)row0 * 80 + seg * 16, Abase + (size_t)row0 * DD + k0);
        cp_async16(ab + (unsigned)row1 * 80 + seg * 16, Abase + (size_t)row1 * DD + k0);
        cp_async16(bb + (unsigned)row0 * 80 + seg * 16, Bw + (size_t)(bn + row0) * DD + k0);
        cp_async16(bb + (unsigned)row1 * 80 + seg * 16, Bw + (size_t)(bn + row1) * DD + k0);
        cp_commit();
    };

    float acc[2][8][4];
#pragma unroll
    for (int mi = 0; mi < 2; mi++)
#pragma unroll
        for (int ni = 0; ni < 8; ni++)
#pragma unroll
            for (int q = 0; q < 4; q++) acc[mi][ni][q] = 0.f;

    load_chunk(0, 0);

    const int NKT = DD / 32;  // 32
    int buf = 0;
    for (int kt = 0; kt < NKT; kt++) {
        if (kt + 1 < NKT) {
            load_chunk(kt + 1, buf ^ 1);  // prev iter's closing barrier protects buf^1
            cp_wait<1>();                 // retires chunk kt
        } else {
            cp_wait<0>();
        }
        __syncthreads();

        const unsigned short* Ab = Ash + buf * GH_TILE;
        const unsigned short* Bb = Bsh + buf * GH_TILE;
#pragma unroll
        for (int ks = 0; ks < 2; ks++) {
            const int k0 = 16 * ks + 2 * t;
            unsigned a[2][4];
#pragma unroll
            for (int mi = 0; mi < 2; mi++) {
                const unsigned short* ap = Ab + (wm0 + 16 * mi + g) * GH_STR;
                a[mi][0] = *(const unsigned*)(ap + k0);
                a[mi][1] = *(const unsigned*)(ap + 8 * GH_STR + k0);
                a[mi][2] = *(const unsigned*)(ap + k0 + 8);
                a[mi][3] = *(const unsigned*)(ap + 8 * GH_STR + k0 + 8);
            }
            unsigned b[8][2];
#pragma unroll
            for (int ni = 0; ni < 8; ni++) {
                const unsigned short* bp = Bb + (wn0 + 8 * ni + g) * GH_STR;
                b[ni][0] = *(const unsigned*)(bp + k0);
                b[ni][1] = *(const unsigned*)(bp + k0 + 8);
            }
#pragma unroll
            for (int mi = 0; mi < 2; mi++)
#pragma unroll
                for (int ni = 0; ni < 8; ni++)
                    mma_f16(acc[mi][ni], a[mi], b[ni]);
        }
        __syncthreads();
        buf ^= 1;
    }

    // Epilogue
#pragma unroll
    for (int mi = 0; mi < 2; mi++) {
#pragma unroll
        for (int ni = 0; ni < 8; ni++) {
            const int c = bn + wn0 + 8 * ni + 2 * t;
            const float2 bb = *(const float2*)&bias[c];
#pragma unroll
            for (int hr = 0; hr < 2; hr++) {
                const int r = bm + wm0 + 16 * mi + g + 8 * hr;
                float vx = acc[mi][ni][2 * hr + 0] + bb.x;
                float vy = acc[mi][ni][2 * hr + 1] + bb.y;
                const int b_ = r >> 11, srow = r & (SS - 1);
                const int h = c >> 6, d = c & (DH - 1);
                if (omode == 0) {
                    *(unsigned*)&g_Qh[(((size_t)b_ * HH + h) * SS + srow) * DH + d] =
                        pack_h2(vx * SCALE_F, vy * SCALE_F);
                } else if (omode == 1) {
                    *(unsigned*)&g_Kh[(((size_t)b_ * HH + h) * SS + srow) * DH + d] =
                        pack_h2(vx, vy);
                } else if (omode == 2) {
                    // V transposed: [B,H,Dh,S]
                    const size_t base = (((size_t)b_ * HH + h) * DH + d) * SS + srow;
                    g_Vh[base]      = f2h(vx);
                    g_Vh[base + SS] = f2h(vy);
                } else {
                    *(float2*)&outp[(size_t)r * DD + c] = make_float2(vx, vy);
                }
            }
        }
    }
}

// ---------------------------------------------------------------------------
// FP16 flash attention:
//  - CTA = 128 q rows of one (b,h), 256 threads (8 warps x 16 rows)
//  - Q fragments register-resident; P stays in registers (S C-frag == P A-frag)
//  - K [s][dh] and V-transposed [dh][s] chunks double-buffered via cp.async
// ---------------------------------------------------------------------------
#define AH_STR 72                       // halfs per smem row
#define AH_QSZ (128*AH_STR)
#define AH_CSZ (64*AH_STR)              // one K or Vt chunk
#define AH_SMEM ((AH_QSZ + 4*AH_CSZ)*2) // 55296 bytes

__global__ __launch_bounds__(256, 2) void attn_h()
{
    extern __shared__ unsigned short smh[];
    unsigned short* Qs  = smh;                       // [128][72]
    unsigned short* Ks  = smh + AH_QSZ;              // [2][64][72]
    unsigned short* Vts = smh + AH_QSZ + 2 * AH_CSZ; // [2][64][72]

    const int qb = blockIdx.x;          // 0..15
    const int bh = blockIdx.y;          // 0..63
    const unsigned short* Qg  = g_Qh + (size_t)bh * SS * DH + (size_t)qb * 128 * DH;
    const unsigned short* Kg  = g_Kh + (size_t)bh * SS * DH;
    const unsigned short* Vtg = g_Vh + (size_t)bh * DH * SS;

    const int tid = threadIdx.x;
    const int warp = tid >> 5, lane = tid & 31;
    const int g = lane >> 2, t = lane & 3;
    const int m0 = warp * 16;

    const unsigned qbase = (unsigned)__cvta_generic_to_shared(Qs);
    const unsigned kbase = (unsigned)__cvta_generic_to_shared(Ks);
    const unsigned vbase = (unsigned)__cvta_generic_to_shared(Vts);

    const int seg = tid & 7;            // 16B (8 halfs) column
    const int qr0 = tid >> 3;           // 0..31
    const int kr0 = tid >> 3, kr1 = kr0 + 32;

    // Q load (one group)
#pragma unroll
    for (int p = 0; p < 4; p++) {
        const int row = qr0 + 32 * p;
        cp_async16(qbase + (unsigned)row * (AH_STR * 2) + seg * 16,
                   Qg + (size_t)row * DH + seg * 8);
    }
    cp_commit();

    auto load_kv = [&](int kv0, int buf) {
        const unsigned kb = kbase + (unsigned)buf * AH_CSZ * 2;
        const unsigned vb = vbase + (unsigned)buf * AH_CSZ * 2;
        cp_async16(kb + (unsigned)kr0 * (AH_STR * 2) + seg * 16,
                   Kg + (size_t)(kv0 + kr0) * DH + seg * 8);
        cp_async16(kb + (unsigned)kr1 * (AH_STR * 2) + seg * 16,
                   Kg + (size_t)(kv0 + kr1) * DH + seg * 8);
        cp_async16(vb + (unsigned)kr0 * (AH_STR * 2) + seg * 16,
                   Vtg + (size_t)kr0 * SS + kv0 + seg * 8);
        cp_async16(vb + (unsigned)kr1 * (AH_STR * 2) + seg * 16,
                   Vtg + (size_t)kr1 * SS + kv0 + seg * 8);
        cp_commit();
    };

    load_kv(0, 0);       // chunk 0 (second group)
    cp_wait<1>();        // Q group done
    __syncthreads();

    // Q fragments -> registers (a-frag per k16 step)
    unsigned qf[4][4];
    {
        const unsigned short* qp = Qs + (m0 + g) * AH_STR;
#pragma unroll
        for (int ks = 0; ks < 4; ks++) {
            const int k0 = 16 * ks + 2 * t;
            qf[ks][0] = *(const unsigned*)(qp + k0);
            qf[ks][1] = *(const unsigned*)(qp + 8 * AH_STR + k0);
            qf[ks][2] = *(const unsigned*)(qp + k0 + 8);
            qf[ks][3] = *(const unsigned*)(qp + 8 * AH_STR + k0 + 8);
        }
    }

    float o[8][4];
#pragma unroll
    for (int ni = 0; ni < 8; ni++)
#pragma unroll
        for (int q = 0; q < 4; q++) o[ni][q] = 0.f;
    float mi0 = -1e30f, mi1 = -1e30f, li0 = 0.f, li1 = 0.f;

    const int NCH = SS / 64;  // 32
    for (int kt = 0; kt < NCH; kt++) {
        const int buf = kt & 1;
        if (kt + 1 < NCH) {
            load_kv((kt + 1) * 64, buf ^ 1);  // closing barrier protects buf^1
            cp_wait<1>();                     // retires chunk kt
        } else {
            cp_wait<0>();
        }
        __syncthreads();

        const unsigned short* Kb  = Ks  + buf * AH_CSZ;
        const unsigned short* Vtb = Vts + buf * AH_CSZ;

        // S = Q K^T : warp 16x64
        float s[8][4];
#pragma unroll
        for (int ni = 0; ni < 8; ni++)
#pragma unroll
            for (int q = 0; q < 4; q++) s[ni][q] = 0.f;

#pragma unroll
        for (int ks = 0; ks < 4; ks++) {
            const int k0 = 16 * ks + 2 * t;
#pragma unroll
            for (int ni = 0; ni < 8; ni++) {
                const unsigned short* kp = Kb + (8 * ni + g) * AH_STR;
                unsigned b[2];
                b[0] = *(const unsigned*)(kp + k0);
                b[1] = *(const unsigned*)(kp + k0 + 8);
                mma_f16(s[ni], qf[ks], b);
            }
        }

        // online softmax; P packed straight into A-fragments (no smem)
        float mx0 = -1e30f, mx1 = -1e30f;
#pragma unroll
        for (int ni = 0; ni < 8; ni++) {
            mx0 = fmaxf(mx0, fmaxf(s[ni][0], s[ni][1]));
            mx1 = fmaxf(mx1, fmaxf(s[ni][2], s[ni][3]));
        }
        mx0 = fmaxf(mx0, __shfl_xor_sync(0xffffffffu, mx0, 1));
        mx0 = fmaxf(mx0, __shfl_xor_sync(0xffffffffu, mx0, 2));
        mx1 = fmaxf(mx1, __shfl_xor_sync(0xffffffffu, mx1, 1));
        mx1 = fmaxf(mx1, __shfl_xor_sync(0xffffffffu, mx1, 2));

        const float mn0 = fmaxf(mi0, mx0), mn1 = fmaxf(mi1, mx1);
        const float corr0 = __expf(mi0 - mn0), corr1 = __expf(mi1 - mn1);
        mi0 = mn0; mi1 = mn1;

        unsigned pa[4][4];
        float rs0 = 0.f, rs1 = 0.f;
#pragma unroll
        for (int ni = 0; ni < 8; ni++) {
            const float p00 = __expf(s[ni][0] - mn0);
            const float p01 = __expf(s[ni][1] - mn0);
            const float p10 = __expf(s[ni][2] - mn1);
            const float p11 = __expf(s[ni][3] - mn1);
            rs0 += p00 + p01;
            rs1 += p10 + p11;
            const int ks = ni >> 1, hi = (ni & 1) << 1;   // tile 2ks(+1)
            pa[ks][hi + 0] = pack_h2(p00, p01);
            pa[ks][hi + 1] = pack_h2(p10, p11);
        }
        rs0 += __shfl_xor_sync(0xffffffffu, rs0, 1);
        rs0 += __shfl_xor_sync(0xffffffffu, rs0, 2);
        rs1 += __shfl_xor_sync(0xffffffffu, rs1, 1);
        rs1 += __shfl_xor_sync(0xffffffffu, rs1, 2);
        li0 = li0 * corr0 + rs0;
        li1 = li1 * corr1 + rs1;
#pragma unroll
        for (int ni = 0; ni < 8; ni++) {
            o[ni][0] *= corr0; o[ni][1] *= corr0;
            o[ni][2] *= corr1; o[ni][3] *= corr1;
        }

        // O += P V : warp 16x64 (B-frags direct from V-transposed)
#pragma unroll
        for (int ks = 0; ks < 4; ks++) {
            const int k0 = 16 * ks + 2 * t;
#pragma unroll
            for (int ni = 0; ni < 8; ni++) {
                const unsigned short* vp = Vtb + (8 * ni + g) * AH_STR;
                unsigned b[2];
                b[0] = *(const unsigned*)(vp + k0);
                b[1] = *(const unsigned*)(vp + k0 + 8);
                mma_f16(o[ni], pa[ks], b);
            }
        }
        __syncthreads();   // all warps done with buf before refill
    }

    // epilogue: normalize, write fp16 g_Oh [B,S,D]
    const int b = bh >> 4, h = bh & 15;
    const float inv0 = 1.f / li0, inv1 = 1.f / li1;
    const int s0 = qb * 128 + m0 + g;
#pragma unroll
    for (int ni = 0; ni < 8; ni++) {
        const int col = h * DH + 8 * ni + 2 * t;
        *(unsigned*)&g_Oh[((size_t)b * SS + s0) * DD + col] =
            pack_h2(o[ni][0] * inv0, o[ni][1] * inv0);
        *(unsigned*)&g_Oh[((size_t)b * SS + s0 + 8) * DD + col] =
            pack_h2(o[ni][2] * inv1, o[ni][3] * inv1);
    }
}

// ---------------------------------------------------------------------------
extern "C" void kernel_launch(void* const* d_in, const int* in_sizes, int n_in,
                              void* d_out, int out_size)
{
    const float* x  = (const float*)d_in[0];
    const float* Wq = (const float*)d_in[1];
    const float* bq = (const float*)d_in[2];
    const float* Wk = (const float*)d_in[3];
    const float* bk = (const float*)d_in[4];
    const float* Wv = (const float*)d_in[5];
    const float* bv = (const float*)d_in[6];
    const float* Wo = (const float*)d_in[7];
    const float* bo = (const float*)d_in[8];
    float* out = (float*)d_out;

    static int configured = 0;
    if (!configured) {
        cudaFuncSetAttribute(gemm_h, cudaFuncAttributeMaxDynamicSharedMemorySize, GH_SMEM);
        cudaFuncSetAttribute(attn_h, cudaFuncAttributeMaxDynamicSharedMemorySize, AH_SMEM);
        configured = 1;
    }

    // pre-pass: fp16 conversions (x elementwise; weights transposed to [N][K])
    cvt_xh<<<(NT * DD) / 2048, 256>>>(x);
    transpose_wh<<<dim3(32, 32), 256>>>(Wq, 0);
    transpose_wh<<<dim3(32, 32), 256>>>(Wk, 1);
    transpose_wh<<<dim3(32, 32), 256>>>(Wv, 2);
    transpose_wh<<<dim3(32, 32), 256>>>(Wo, 3);

    dim3 gg(DD / 128, NT / 128);  // (8, 64)
    gemm_h<<<gg, 256, GH_SMEM>>>(bq, nullptr, 0, 0, 0);
    gemm_h<<<gg, 256, GH_SMEM>>>(bk, nullptr, 0, 1, 1);
    gemm_h<<<gg, 256, GH_SMEM>>>(bv, nullptr, 0, 2, 2);

    attn_h<<<dim3(SS / 128, BB * HH), 256, AH_SMEM>>>();

    gemm_h<<<gg, 256, GH_SMEM>>>(bo, out, 1, 3, 3);
}

// round 8
// speedup vs baseline: 1.8351x; 1.0570x over previous
#include <cuda_runtime.h>
#include <math.h>

// Problem constants
#define BB 4
#define SS 2048
#define DD 1024
#define HH 16
#define DH 64
#define NT (BB*SS)          // 8192 tokens
#define SCALE_F 0.125f      // 64^-0.5

// Scratch (device globals; fp16 stored as u16)
__device__ unsigned short g_Qh[(size_t)BB*HH*SS*DH];  // [B,H,S,Dh], pre-scaled
__device__ unsigned short g_Kh[(size_t)BB*HH*SS*DH];  // [B,H,S,Dh]
__device__ unsigned short g_Vh[(size_t)BB*HH*DH*SS];  // [B,H,Dh,S]  (transposed)
__device__ unsigned short g_Oh[(size_t)NT*DD];        // [B,S,D]
__device__ unsigned short g_Xh[(size_t)NT*DD];        // fp16 x
__device__ unsigned short g_Wh[(size_t)4*DD*DD];      // fp16 weights, [N][K], q|k|v|o

// ---------------------------------------------------------------------------
// helpers
// ---------------------------------------------------------------------------
__device__ __forceinline__ unsigned pack_h2(float lo, float hi) {
    unsigned u;
    asm("cvt.rn.f16x2.f32 %0, %1, %2;" : "=r"(u) : "f"(hi), "f"(lo));
    return u;
}
__device__ __forceinline__ unsigned short f2h(float x) {
    unsigned short h;
    asm("cvt.rn.f16.f32 %0, %1;" : "=h"(h) : "f"(x));
    return h;
}

__device__ __forceinline__ void mma_f16(float* c, const unsigned* a, const unsigned* b) {
    asm volatile(
        "mma.sync.aligned.m16n8k16.row.col.f32.f16.f16.f32 "
        "{%0,%1,%2,%3}, {%4,%5,%6,%7}, {%8,%9}, {%0,%1,%2,%3};\n"
        : "+f"(c[0]), "+f"(c[1]), "+f"(c[2]), "+f"(c[3])
        : "r"(a[0]), "r"(a[1]), "r"(a[2]), "r"(a[3]),
          "r"(b[0]), "r"(b[1]));
}

__device__ __forceinline__ void cp_async16(unsigned smem_addr, const void* gptr) {
    asm volatile("cp.async.ca.shared.global [%0], [%1], 16;\n"
                 :: "r"(smem_addr), "l"(gptr));
}
__device__ __forceinline__ void cp_commit() {
    asm volatile("cp.async.commit_group;\n" ::: "memory");
}
template<int N>
__device__ __forceinline__ void cp_wait() {
    asm volatile("cp.async.wait_group %0;\n" :: "n"(N) : "memory");
}

// ---------------------------------------------------------------------------
// Fused pre-pass: blocks [0,4096) convert x f32->f16;
// blocks [4096,8192) transpose one 32x32 tile of one weight to [N][K] fp16.
// ---------------------------------------------------------------------------
__global__ __launch_bounds__(256) void prep(
    const float* __restrict__ x,
    const float* __restrict__ Wq, const float* __restrict__ Wk,
    const float* __restrict__ Wv, const float* __restrict__ Wo)
{
    __shared__ float t[32][33];
    const int gid = blockIdx.x;
    if (gid < 4096) {
        const size_t i = ((size_t)gid * 256 + threadIdx.x) * 8;
        float4 v0 = *(const float4*)&x[i];
        float4 v1 = *(const float4*)&x[i + 4];
        uint4 o;
        o.x = pack_h2(v0.x, v0.y);
        o.y = pack_h2(v0.z, v0.w);
        o.z = pack_h2(v1.x, v1.y);
        o.w = pack_h2(v1.z, v1.w);
        *(uint4*)&g_Xh[i] = o;
    } else {
        const int tt = gid - 4096;
        const int widx = tt >> 10;
        const float* W = (widx == 0) ? Wq : (widx == 1) ? Wk : (widx == 2) ? Wv : Wo;
        unsigned short* Wt = g_Wh + (size_t)widx * DD * DD;
        const int n0 = (tt & 31) * 32, k0 = ((tt >> 5) & 31) * 32;
        const int tx = threadIdx.x & 31, ty = threadIdx.x >> 5;   // 32x8
#pragma unroll
        for (int i = 0; i < 4; i++)
            t[ty + 8 * i][tx] = W[(size_t)(k0 + ty + 8 * i) * DD + n0 + tx];
        __syncthreads();
#pragma unroll
        for (int i = 0; i < 4; i++)
            Wt[(size_t)(n0 + ty + 8 * i) * DD + k0 + tx] = f2h(t[tx][ty + 8 * i]);
    }
}

// ---------------------------------------------------------------------------
// FP16 GEMM core pieces (shared by fused-QKV and output GEMM)
// 128x128 tiles, K-chunks of 32, 256 threads (8 warps, warp 32x64),
// triple-buffered cp.async (ONE barrier per iteration), mma.m16n8k16.
//  A smem: [128][40] half ; B smem (weights [N][K]): [128][40] half
// ---------------------------------------------------------------------------
#define GH_STR 40
#define GH_TILE (128*GH_STR)               // halfs per tensor per buffer
#define GH_SMEM (3*2*GH_TILE*2)            // 61440 bytes

// ---- fused QKV GEMM: N = 3072 (regions: 0=Q,1=K,2=V) --------------------
__global__ __launch_bounds__(256, 2) void gemm_qkv(
    const float* __restrict__ bq, const float* __restrict__ bk,
    const float* __restrict__ bv)
{
    extern __shared__ unsigned short smem_h[];
    unsigned short* Ash = smem_h;                    // [3][128][40]
    unsigned short* Bsh = smem_h + 3 * GH_TILE;      // [3][128][40]
    const unsigned abase = (unsigned)__cvta_generic_to_shared(Ash);
    const unsigned bbase = (unsigned)__cvta_generic_to_shared(Bsh);

    const int bm = blockIdx.y * 128;
    const int bn = blockIdx.x * 128;                 // 0..2944 (global N=3072)
    const int region = bn >> 10;
    const float* bias = (region == 0) ? bq : (region == 1) ? bk : bv;

    const int tid = threadIdx.x;
    const int warp = tid >> 5, lane = tid & 31;
    const int g = lane >> 2, t = lane & 3;
    const int wm0 = (warp >> 1) * 32;
    const int wn0 = (warp & 1) * 64;

    const int seg = tid & 3;
    const int row0 = tid >> 2, row1 = row0 + 64;
    const unsigned short* Abase = g_Xh + (size_t)bm * DD;
    const unsigned short* Bw = g_Wh;                 // q|k|v contiguous: row = bn+row

    auto load_chunk = [&](int kt, int buf) {
        const int k0 = kt * 32 + seg * 8;
        const unsigned ab = abase + (unsigned)buf * GH_TILE * 2;
        const unsigned bb = bbase + (unsigned)buf * GH_TILE * 2;
        cp_async16(ab + (unsigned)row0 * 80 + seg * 16, Abase + (size_t)row0 * DD + k0);
        cp_async16(ab + (unsigned)row1 * 80 + seg * 16, Abase + (size_t)row1 * DD + k0);
        cp_async16(bb + (unsigned)row0 * 80 + seg * 16, Bw + (size_t)(bn + row0) * DD + k0);
        cp_async16(bb + (unsigned)row1 * 80 + seg * 16, Bw + (size_t)(bn + row1) * DD + k0);
        cp_commit();
    };

    float acc[2][8][4];
#pragma unroll
    for (int mi = 0; mi < 2; mi++)
#pragma unroll
        for (int ni = 0; ni < 8; ni++)
#pragma unroll
            for (int q = 0; q < 4; q++) acc[mi][ni][q] = 0.f;

    load_chunk(0, 0);
    load_chunk(1, 1);

    const int NKT = DD / 32;  // 32
    for (int kt = 0; kt < NKT; kt++) {
        if (kt + 1 < NKT) { cp_wait<1>(); } else { cp_wait<0>(); }
        __syncthreads();                       // all warps done with iter kt-1
        if (kt + 2 < NKT) load_chunk(kt + 2, (kt + 2) % 3);

        const int buf = kt % 3;
        const unsigned short* Ab = Ash + buf * GH_TILE;
        const unsigned short* Bb = Bsh + buf * GH_TILE;
#pragma unroll
        for (int ks = 0; ks < 2; ks++) {
            const int k0 = 16 * ks + 2 * t;
            unsigned a[2][4];
#pragma unroll
            for (int mi = 0; mi < 2; mi++) {
                const unsigned short* ap = Ab + (wm0 + 16 * mi + g) * GH_STR;
                a[mi][0] = *(const unsigned*)(ap + k0);
                a[mi][1] = *(const unsigned*)(ap + 8 * GH_STR + k0);
                a[mi][2] = *(const unsigned*)(ap + k0 + 8);
                a[mi][3] = *(const unsigned*)(ap + 8 * GH_STR + k0 + 8);
            }
            unsigned b[8][2];
#pragma unroll
            for (int ni = 0; ni < 8; ni++) {
                const unsigned short* bp = Bb + (wn0 + 8 * ni + g) * GH_STR;
                b[ni][0] = *(const unsigned*)(bp + k0);
                b[ni][1] = *(const unsigned*)(bp + k0 + 8);
            }
#pragma unroll
            for (int mi = 0; mi < 2; mi++)
#pragma unroll
                for (int ni = 0; ni < 8; ni++)
                    mma_f16(acc[mi][ni], a[mi], b[ni]);
        }
    }

    // Epilogue (region decides destination layout)
#pragma unroll
    for (int mi = 0; mi < 2; mi++) {
#pragma unroll
        for (int ni = 0; ni < 8; ni++) {
            const int c = bn + wn0 + 8 * ni + 2 * t;
            const int cc = c & 1023;
            const float2 bb = *(const float2*)&bias[cc];
#pragma unroll
            for (int hr = 0; hr < 2; hr++) {
                const int r = bm + wm0 + 16 * mi + g + 8 * hr;
                float vx = acc[mi][ni][2 * hr + 0] + bb.x;
                float vy = acc[mi][ni][2 * hr + 1] + bb.y;
                const int b_ = r >> 11, srow = r & (SS - 1);
                const int h = cc >> 6, d = cc & (DH - 1);
                if (region == 0) {
                    *(unsigned*)&g_Qh[(((size_t)b_ * HH + h) * SS + srow) * DH + d] =
                        pack_h2(vx * SCALE_F, vy * SCALE_F);
                } else if (region == 1) {
                    *(unsigned*)&g_Kh[(((size_t)b_ * HH + h) * SS + srow) * DH + d] =
                        pack_h2(vx, vy);
                } else {
                    const size_t base = (((size_t)b_ * HH + h) * DH + d) * SS + srow;
                    g_Vh[base]      = f2h(vx);
                    g_Vh[base + SS] = f2h(vy);
                }
            }
        }
    }
}

// ---- output GEMM: A = g_Oh, W = g_Wh[3], f32 out + bias ------------------
__global__ __launch_bounds__(256, 2) void gemm_o(
    const float* __restrict__ bias, float* __restrict__ outp)
{
    extern __shared__ unsigned short smem_h[];
    unsigned short* Ash = smem_h;
    unsigned short* Bsh = smem_h + 3 * GH_TILE;
    const unsigned abase = (unsigned)__cvta_generic_to_shared(Ash);
    const unsigned bbase = (unsigned)__cvta_generic_to_shared(Bsh);

    const int bm = blockIdx.y * 128;
    const int bn = blockIdx.x * 128;
    const int tid = threadIdx.x;
    const int warp = tid >> 5, lane = tid & 31;
    const int g = lane >> 2, t = lane & 3;
    const int wm0 = (warp >> 1) * 32;
    const int wn0 = (warp & 1) * 64;

    const int seg = tid & 3;
    const int row0 = tid >> 2, row1 = row0 + 64;
    const unsigned short* Abase = g_Oh + (size_t)bm * DD;
    const unsigned short* Bw = g_Wh + (size_t)3 * DD * DD;

    auto load_chunk = [&](int kt, int buf) {
        const int k0 = kt * 32 + seg * 8;
        const unsigned ab = abase + (unsigned)buf * GH_TILE * 2;
        const unsigned bb = bbase + (unsigned)buf * GH_TILE * 2;
        cp_async16(ab + (unsigned)row0 * 80 + seg * 16, Abase + (size_t)row0 * DD + k0);
        cp_async16(ab + (unsigned)row1 * 80 + seg * 16, Abase + (size_t)row1 * DD + k0);
        cp_async16(bb + (unsigned)row0 * 80 + seg * 16, Bw + (size_t)(bn + row0) * DD + k0);
        cp_async16(bb + (unsigned)row1 * 80 + seg * 16, Bw + (size_t)(bn + row1) * DD + k0);
        cp_commit();
    };

    float acc[2][8][4];
#pragma unroll
    for (int mi = 0; mi < 2; mi++)
#pragma unroll
        for (int ni = 0; ni < 8; ni++)
#pragma unroll
            for (int q = 0; q < 4; q++) acc[mi][ni][q] = 0.f;

    load_chunk(0, 0);
    load_chunk(1, 1);

    const int NKT = DD / 32;
    for (int kt = 0; kt < NKT; kt++) {
        if (kt + 1 < NKT) { cp_wait<1>(); } else { cp_wait<0>(); }
        __syncthreads();
        if (kt + 2 < NKT) load_chunk(kt + 2, (kt + 2) % 3);

        const int buf = kt % 3;
        const unsigned short* Ab = Ash + buf * GH_TILE;
        const unsigned short* Bb = Bsh + buf * GH_TILE;
#pragma unroll
        for (int ks = 0; ks < 2; ks++) {
            const int k0 = 16 * ks + 2 * t;
            unsigned a[2][4];
#pragma unroll
            for (int mi = 0; mi < 2; mi++) {
                const unsigned short* ap = Ab + (wm0 + 16 * mi + g) * GH_STR;
                a[mi][0] = *(const unsigned*)(ap + k0);
                a[mi][1] = *(const unsigned*)(ap + 8 * GH_STR + k0);
                a[mi][2] = *(const unsigned*)(ap + k0 + 8);
                a[mi][3] = *(const unsigned*)(ap + 8 * GH_STR + k0 + 8);
            }
            unsigned b[8][2];
#pragma unroll
            for (int ni = 0; ni < 8; ni++) {
                const unsigned short* bp = Bb + (wn0 + 8 * ni + g) * GH_STR;
                b[ni][0] = *(const unsigned*)(bp + k0);
                b[ni][1] = *(const unsigned*)(bp + k0 + 8);
            }
#pragma unroll
            for (int mi = 0; mi < 2; mi++)
#pragma unroll
                for (int ni = 0; ni < 8; ni++)
                    mma_f16(acc[mi][ni], a[mi], b[ni]);
        }
    }

#pragma unroll
    for (int mi = 0; mi < 2; mi++) {
#pragma unroll
        for (int ni = 0; ni < 8; ni++) {
            const int c = bn + wn0 + 8 * ni + 2 * t;
            const float2 bb = *(const float2*)&bias[c];
#pragma unroll
            for (int hr = 0; hr < 2; hr++) {
                const int r = bm + wm0 + 16 * mi + g + 8 * hr;
                *(float2*)&outp[(size_t)r * DD + c] =
                    make_float2(acc[mi][ni][2 * hr + 0] + bb.x,
                                acc[mi][ni][2 * hr + 1] + bb.y);
            }
        }
    }
}

// ---------------------------------------------------------------------------
// FP16 flash attention (triple-buffered K/V, one barrier per chunk):
//  - CTA = 128 q rows of one (b,h), 256 threads (8 warps x 16 rows)
//  - Q fragments register-resident; P stays in registers
// ---------------------------------------------------------------------------
#define AH_STR 72                       // halfs per smem row
#define AH_QSZ (128*AH_STR)
#define AH_CSZ (64*AH_STR)              // one K or Vt chunk
#define AH_SMEM ((AH_QSZ + 6*AH_CSZ)*2) // 73728 bytes

__global__ __launch_bounds__(256, 2) void attn_h()
{
    extern __shared__ unsigned short smh[];
    unsigned short* Qs  = smh;                       // [128][72]
    unsigned short* Ks  = smh + AH_QSZ;              // [3][64][72]
    unsigned short* Vts = smh + AH_QSZ + 3 * AH_CSZ; // [3][64][72]

    const int qb = blockIdx.x;          // 0..15
    const int bh = blockIdx.y;          // 0..63
    const unsigned short* Qg  = g_Qh + (size_t)bh * SS * DH + (size_t)qb * 128 * DH;
    const unsigned short* Kg  = g_Kh + (size_t)bh * SS * DH;
    const unsigned short* Vtg = g_Vh + (size_t)bh * DH * SS;

    const int tid = threadIdx.x;
    const int warp = tid >> 5, lane = tid & 31;
    const int g = lane >> 2, t = lane & 3;
    const int m0 = warp * 16;

    const unsigned qbase = (unsigned)__cvta_generic_to_shared(Qs);
    const unsigned kbase = (unsigned)__cvta_generic_to_shared(Ks);
    const unsigned vbase = (unsigned)__cvta_generic_to_shared(Vts);

    const int seg = tid & 7;            // 16B (8 halfs) column
    const int r0 = tid >> 3, r1 = r0 + 32;

    // Q load (group 0)
#pragma unroll
    for (int p = 0; p < 4; p++) {
        const int row = r0 + 32 * p;
        cp_async16(qbase + (unsigned)row * (AH_STR * 2) + seg * 16,
                   Qg + (size_t)row * DH + seg * 8);
    }
    cp_commit();

    auto load_kv = [&](int kv0, int buf) {
        const unsigned kb = kbase + (unsigned)buf * AH_CSZ * 2;
        const unsigned vb = vbase + (unsigned)buf * AH_CSZ * 2;
        cp_async16(kb + (unsigned)r0 * (AH_STR * 2) + seg * 16,
                   Kg + (size_t)(kv0 + r0) * DH + seg * 8);
        cp_async16(kb + (unsigned)r1 * (AH_STR * 2) + seg * 16,
                   Kg + (size_t)(kv0 + r1) * DH + seg * 8);
        cp_async16(vb + (unsigned)r0 * (AH_STR * 2) + seg * 16,
                   Vtg + (size_t)r0 * SS + kv0 + seg * 8);
        cp_async16(vb + (unsigned)r1 * (AH_STR * 2) + seg * 16,
                   Vtg + (size_t)r1 * SS + kv0 + seg * 8);
        cp_commit();
    };

    load_kv(0, 0);        // group 1
    load_kv(64, 1);       // group 2
    cp_wait<2>();         // Q landed
    __syncthreads();

    // Q fragments -> registers
    unsigned qf[4][4];
    {
        const unsigned short* qp = Qs + (m0 + g) * AH_STR;
#pragma unroll
        for (int ks = 0; ks < 4; ks++) {
            const int k0 = 16 * ks + 2 * t;
            qf[ks][0] = *(const unsigned*)(qp + k0);
            qf[ks][1] = *(const unsigned*)(qp + 8 * AH_STR + k0);
            qf[ks][2] = *(const unsigned*)(qp + k0 + 8);
            qf[ks][3] = *(const unsigned*)(qp + 8 * AH_STR + k0 + 8);
        }
    }

    float o[8][4];
#pragma unroll
    for (int ni = 0; ni < 8; ni++)
#pragma unroll
        for (int q = 0; q < 4; q++) o[ni][q] = 0.f;
    float mi0 = -1e30f, mi1 = -1e30f, li0 = 0.f, li1 = 0.f;

    const int NCH = SS / 64;  // 32
    for (int kt = 0; kt < NCH; kt++) {
        if (kt + 1 < NCH) { cp_wait<1>(); } else { cp_wait<0>(); }
        __syncthreads();                     // all warps done with iter kt-1
        if (kt + 2 < NCH) load_kv((kt + 2) * 64, (kt + 2) % 3);

        const int buf = kt % 3;
        const unsigned short* Kb  = Ks  + buf * AH_CSZ;
        const unsigned short* Vtb = Vts + buf * AH_CSZ;

        // S = Q K^T : warp 16x64
        float s[8][4];
#pragma unroll
        for (int ni = 0; ni < 8; ni++)
#pragma unroll
            for (int q = 0; q < 4; q++) s[ni][q] = 0.f;

#pragma unroll
        for (int ks = 0; ks < 4; ks++) {
            const int k0 = 16 * ks + 2 * t;
#pragma unroll
            for (int ni = 0; ni < 8; ni++) {
                const unsigned short* kp = Kb + (8 * ni + g) * AH_STR;
                unsigned b[2];
                b[0] = *(const unsigned*)(kp + k0);
                b[1] = *(const unsigned*)(kp + k0 + 8);
                mma_f16(s[ni], qf[ks], b);
            }
        }

        // online softmax; P packed straight into A-fragments (no smem)
        float mx0 = -1e30f, mx1 = -1e30f;
#pragma unroll
        for (int ni = 0; ni < 8; ni++) {
            mx0 = fmaxf(mx0, fmaxf(s[ni][0], s[ni][1]));
            mx1 = fmaxf(mx1, fmaxf(s[ni][2], s[ni][3]));
        }
        mx0 = fmaxf(mx0, __shfl_xor_sync(0xffffffffu, mx0, 1));
        mx0 = fmaxf(mx0, __shfl_xor_sync(0xffffffffu, mx0, 2));
        mx1 = fmaxf(mx1, __shfl_xor_sync(0xffffffffu, mx1, 1));
        mx1 = fmaxf(mx1, __shfl_xor_sync(0xffffffffu, mx1, 2));

        const float mn0 = fmaxf(mi0, mx0), mn1 = fmaxf(mi1, mx1);
        const float corr0 = __expf(mi0 - mn0), corr1 = __expf(mi1 - mn1);
        mi0 = mn0; mi1 = mn1;

        unsigned pa[4][4];
        float rs0 = 0.f, rs1 = 0.f;
#pragma unroll
        for (int ni = 0; ni < 8; ni++) {
            const float p00 = __expf(s[ni][0] - mn0);
            const float p01 = __expf(s[ni][1] - mn0);
            const float p10 = __expf(s[ni][2] - mn1);
            const float p11 = __expf(s[ni][3] - mn1);
            rs0 += p00 + p01;
            rs1 += p10 + p11;
            const int ks = ni >> 1, hi = (ni & 1) << 1;
            pa[ks][hi + 0] = pack_h2(p00, p01);
            pa[ks][hi + 1] = pack_h2(p10, p11);
        }
        rs0 += __shfl_xor_sync(0xffffffffu, rs0, 1);
        rs0 += __shfl_xor_sync(0xffffffffu, rs0, 2);
        rs1 += __shfl_xor_sync(0xffffffffu, rs1, 1);
        rs1 += __shfl_xor_sync(0xffffffffu, rs1, 2);
        li0 = li0 * corr0 + rs0;
        li1 = li1 * corr1 + rs1;
#pragma unroll
        for (int ni = 0; ni < 8; ni++) {
            o[ni][0] *= corr0; o[ni][1] *= corr0;
            o[ni][2] *= corr1; o[ni][3] *= corr1;
        }

        // O += P V : warp 16x64 (B-frags direct from V-transposed)
#pragma unroll
        for (int ks = 0; ks < 4; ks++) {
            const int k0 = 16 * ks + 2 * t;
#pragma unroll
            for (int ni = 0; ni < 8; ni++) {
                const unsigned short* vp = Vtb + (8 * ni + g) * AH_STR;
                unsigned b[2];
                b[0] = *(const unsigned*)(vp + k0);
                b[1] = *(const unsigned*)(vp + k0 + 8);
                mma_f16(o[ni], pa[ks], b);
            }
        }
    }

    // epilogue: normalize, write fp16 g_Oh [B,S,D]
    const int b = bh >> 4, h = bh & 15;
    const float inv0 = 1.f / li0, inv1 = 1.f / li1;
    const int s0 = qb * 128 + m0 + g;
#pragma unroll
    for (int ni = 0; ni < 8; ni++) {
        const int col = h * DH + 8 * ni + 2 * t;
        *(unsigned*)&g_Oh[((size_t)b * SS + s0) * DD + col] =
            pack_h2(o[ni][0] * inv0, o[ni][1] * inv0);
        *(unsigned*)&g_Oh[((size_t)b * SS + s0 + 8) * DD + col] =
            pack_h2(o[ni][2] * inv1, o[ni][3] * inv1);
    }
}

// ---------------------------------------------------------------------------
extern "C" void kernel_launch(void* const* d_in, const int* in_sizes, int n_in,
                              void* d_out, int out_size)
{
    const float* x  = (const float*)d_in[0];
    const float* Wq = (const float*)d_in[1];
    const float* bq = (const float*)d_in[2];
    const float* Wk = (const float*)d_in[3];
    const float* bk = (const float*)d_in[4];
    const float* Wv = (const float*)d_in[5];
    const float* bv = (const float*)d_in[6];
    const float* Wo = (const float*)d_in[7];
    const float* bo = (const float*)d_in[8];
    float* out = (float*)d_out;

    static int configured = 0;
    if (!configured) {
        cudaFuncSetAttribute(gemm_qkv, cudaFuncAttributeMaxDynamicSharedMemorySize, GH_SMEM);
        cudaFuncSetAttribute(gemm_o,   cudaFuncAttributeMaxDynamicSharedMemorySize, GH_SMEM);
        cudaFuncSetAttribute(attn_h,   cudaFuncAttributeMaxDynamicSharedMemorySize, AH_SMEM);
        configured = 1;
    }

    prep<<<8192, 256>>>(x, Wq, Wk, Wv, Wo);
    gemm_qkv<<<dim3(24, 64), 256, GH_SMEM>>>(bq, bk, bv);
    attn_h<<<dim3(SS / 128, BB * HH), 256, AH_SMEM>>>();
    gemm_o<<<dim3(8, 64), 256, GH_SMEM>>>(bo, out);
}

// round 9
// speedup vs baseline: 2.1138x; 1.1519x over previous
#include <cuda_runtime.h>
#include <math.h>

// Problem constants
#define BB 4
#define SS 2048
#define DD 1024
#define HH 16
#define DH 64
#define NT (BB*SS)          // 8192 tokens
#define SCALE_F 0.125f      // 64^-0.5
#define SCALE_L2 (0.125f * 1.44269504088896f)   // includes log2(e) for ex2 softmax

// Scratch (device globals; fp16 stored as u16)
__device__ unsigned short g_Qh[(size_t)BB*HH*SS*DH];  // [B,H,S,Dh], pre-scaled by SCALE_L2
__device__ unsigned short g_Kh[(size_t)BB*HH*SS*DH];  // [B,H,S,Dh]
__device__ unsigned short g_Vh[(size_t)BB*HH*DH*SS];  // [B,H,Dh,S]  (transposed)
__device__ unsigned short g_Oh[(size_t)NT*DD];        // [B,S,D]
__device__ unsigned short g_Xh[(size_t)NT*DD];        // fp16 x
__device__ unsigned short g_Wh[(size_t)4*DD*DD];      // fp16 weights, [N][K], q|k|v|o

// ---------------------------------------------------------------------------
// helpers
// ---------------------------------------------------------------------------
__device__ __forceinline__ unsigned pack_h2(float lo, float hi) {
    unsigned u;
    asm("cvt.rn.f16x2.f32 %0, %1, %2;" : "=r"(u) : "f"(hi), "f"(lo));
    return u;
}
__device__ __forceinline__ unsigned short f2h(float x) {
    unsigned short h;
    asm("cvt.rn.f16.f32 %0, %1;" : "=h"(h) : "f"(x));
    return h;
}
__device__ __forceinline__ float ex2(float x) {
    float y;
    asm("ex2.approx.f32 %0, %1;" : "=f"(y) : "f"(x));
    return y;
}

__device__ __forceinline__ void mma_f16(float* c, const unsigned* a, const unsigned* b) {
    asm volatile(
        "mma.sync.aligned.m16n8k16.row.col.f32.f16.f16.f32 "
        "{%0,%1,%2,%3}, {%4,%5,%6,%7}, {%8,%9}, {%0,%1,%2,%3};\n"
        : "+f"(c[0]), "+f"(c[1]), "+f"(c[2]), "+f"(c[3])
        : "r"(a[0]), "r"(a[1]), "r"(a[2]), "r"(a[3]),
          "r"(b[0]), "r"(b[1]));
}

__device__ __forceinline__ void ldsm_x4(unsigned* d, unsigned addr) {
    asm volatile("ldmatrix.sync.aligned.m8n8.x4.shared.b16 {%0,%1,%2,%3}, [%4];"
        : "=r"(d[0]), "=r"(d[1]), "=r"(d[2]), "=r"(d[3]) : "r"(addr));
}

__device__ __forceinline__ void cp_async16(unsigned smem_addr, const void* gptr) {
    asm volatile("cp.async.ca.shared.global [%0], [%1], 16;\n"
                 :: "r"(smem_addr), "l"(gptr));
}
__device__ __forceinline__ void cp_commit() {
    asm volatile("cp.async.commit_group;\n" ::: "memory");
}
template<int N>
__device__ __forceinline__ void cp_wait() {
    asm volatile("cp.async.wait_group %0;\n" :: "n"(N) : "memory");
}

// ---------------------------------------------------------------------------
// Fused pre-pass: blocks [0,4096) convert x f32->f16;
// blocks [4096,8192) transpose one 32x32 tile of one weight to [N][K] fp16.
// ---------------------------------------------------------------------------
__global__ __launch_bounds__(256) void prep(
    const float* __restrict__ x,
    const float* __restrict__ Wq, const float* __restrict__ Wk,
    const float* __restrict__ Wv, const float* __restrict__ Wo)
{
    __shared__ float t[32][33];
    const int gid = blockIdx.x;
    if (gid < 4096) {
        const size_t i = ((size_t)gid * 256 + threadIdx.x) * 8;
        float4 v0 = *(const float4*)&x[i];
        float4 v1 = *(const float4*)&x[i + 4];
        uint4 o;
        o.x = pack_h2(v0.x, v0.y);
        o.y = pack_h2(v0.z, v0.w);
        o.z = pack_h2(v1.x, v1.y);
        o.w = pack_h2(v1.z, v1.w);
        *(uint4*)&g_Xh[i] = o;
    } else {
        const int tt = gid - 4096;
        const int widx = tt >> 10;
        const float* W = (widx == 0) ? Wq : (widx == 1) ? Wk : (widx == 2) ? Wv : Wo;
        unsigned short* Wt = g_Wh + (size_t)widx * DD * DD;
        const int n0 = (tt & 31) * 32, k0 = ((tt >> 5) & 31) * 32;
        const int tx = threadIdx.x & 31, ty = threadIdx.x >> 5;   // 32x8
#pragma unroll
        for (int i = 0; i < 4; i++)
            t[ty + 8 * i][tx] = W[(size_t)(k0 + ty + 8 * i) * DD + n0 + tx];
        __syncthreads();
#pragma unroll
        for (int i = 0; i < 4; i++)
            Wt[(size_t)(n0 + ty + 8 * i) * DD + k0 + tx] = f2h(t[tx][ty + 8 * i]);
    }
}

// ---------------------------------------------------------------------------
// FP16 GEMM: 128x128 tiles, K-chunks of 32, 256 threads (8 warps, warp 32x64),
// triple-buffered cp.async, ldmatrix fragment loads, mma.m16n8k16.
// ---------------------------------------------------------------------------
#define GH_STR 40
#define GH_TILE (128*GH_STR)               // halfs per tensor per buffer
#define GH_SMEM (3*2*GH_TILE*2)            // 61440 bytes

// ---- fused QKV GEMM: N = 3072 (regions: 0=Q,1=K,2=V) --------------------
__global__ __launch_bounds__(256, 2) void gemm_qkv(
    const float* __restrict__ bq, const float* __restrict__ bk,
    const float* __restrict__ bv)
{
    extern __shared__ unsigned short smem_h[];
    unsigned short* Ash = smem_h;                    // [3][128][40]
    unsigned short* Bsh = smem_h + 3 * GH_TILE;      // [3][128][40]
    const unsigned abase = (unsigned)__cvta_generic_to_shared(Ash);
    const unsigned bbase = (unsigned)__cvta_generic_to_shared(Bsh);

    const int bm = blockIdx.y * 128;
    const int bn = blockIdx.x * 128;                 // 0..2944 (global N=3072)
    const int region = bn >> 10;
    const float* bias = (region == 0) ? bq : (region == 1) ? bk : bv;

    const int tid = threadIdx.x;
    const int warp = tid >> 5, lane = tid & 31;
    const int g = lane >> 2, t = lane & 3;
    const int wm0 = (warp >> 1) * 32;
    const int wn0 = (warp & 1) * 64;

    // ldmatrix per-lane offsets
    const int q4 = lane >> 3, rr = lane & 7;
    unsigned aoff[2], boff[4];
#pragma unroll
    for (int mi = 0; mi < 2; mi++)
        aoff[mi] = ((unsigned)(wm0 + 16 * mi + ((q4 & 1) << 3) + rr) * GH_STR
                    + ((q4 >> 1) << 3)) * 2;
#pragma unroll
    for (int j = 0; j < 4; j++)
        boff[j] = ((unsigned)(wn0 + 16 * j + ((q4 >> 1) << 3) + rr) * GH_STR
                   + ((q4 & 1) << 3)) * 2;

    const int seg = tid & 3;
    const int row0 = tid >> 2, row1 = row0 + 64;
    const unsigned short* Abase = g_Xh + (size_t)bm * DD;
    const unsigned short* Bw = g_Wh;                 // q|k|v contiguous

    auto load_chunk = [&](int kt, int buf) {
        const int k0 = kt * 32 + seg * 8;
        const unsigned ab = abase + (unsigned)buf * GH_TILE * 2;
        const unsigned bb = bbase + (unsigned)buf * GH_TILE * 2;
        cp_async16(ab + (unsigned)row0 * 80 + seg * 16, Abase + (size_t)row0 * DD + k0);
        cp_async16(ab + (unsigned)row1 * 80 + seg * 16, Abase + (size_t)row1 * DD + k0);
        cp_async16(bb + (unsigned)row0 * 80 + seg * 16, Bw + (size_t)(bn + row0) * DD + k0);
        cp_async16(bb + (unsigned)row1 * 80 + seg * 16, Bw + (size_t)(bn + row1) * DD + k0);
        cp_commit();
    };

    float acc[2][8][4];
#pragma unroll
    for (int mi = 0; mi < 2; mi++)
#pragma unroll
        for (int ni = 0; ni < 8; ni++)
#pragma unroll
            for (int q = 0; q < 4; q++) acc[mi][ni][q] = 0.f;

    load_chunk(0, 0);
    load_chunk(1, 1);

    const int NKT = DD / 32;  // 32
    for (int kt = 0; kt < NKT; kt++) {
        if (kt + 1 < NKT) { cp_wait<1>(); } else { cp_wait<0>(); }
        __syncthreads();
        if (kt + 2 < NKT) load_chunk(kt + 2, (kt + 2) % 3);

        const int buf = kt % 3;
        const unsigned aB = abase + (unsigned)buf * GH_TILE * 2;
        const unsigned bB = bbase + (unsigned)buf * GH_TILE * 2;
#pragma unroll
        for (int ks = 0; ks < 2; ks++) {
            const unsigned kb = (unsigned)(32 * ks);   // 16 halfs * 2B
            unsigned a[2][4], bt[4][4];
            ldsm_x4(a[0], aB + aoff[0] + kb);
            ldsm_x4(a[1], aB + aoff[1] + kb);
#pragma unroll
            for (int j = 0; j < 4; j++)
                ldsm_x4(bt[j], bB + boff[j] + kb);
#pragma unroll
            for (int mi = 0; mi < 2; mi++)
#pragma unroll
                for (int ni = 0; ni < 8; ni++)
                    mma_f16(acc[mi][ni], a[mi], &bt[ni >> 1][(ni & 1) << 1]);
        }
    }

    // Epilogue (region decides destination layout)
#pragma unroll
    for (int mi = 0; mi < 2; mi++) {
#pragma unroll
        for (int ni = 0; ni < 8; ni++) {
            const int c = bn + wn0 + 8 * ni + 2 * t;
            const int cc = c & 1023;
            const float2 bb = *(const float2*)&bias[cc];
#pragma unroll
            for (int hr = 0; hr < 2; hr++) {
                const int r = bm + wm0 + 16 * mi + g + 8 * hr;
                float vx = acc[mi][ni][2 * hr + 0] + bb.x;
                float vy = acc[mi][ni][2 * hr + 1] + bb.y;
                const int b_ = r >> 11, srow = r & (SS - 1);
                const int h = cc >> 6, d = cc & (DH - 1);
                if (region == 0) {
                    *(unsigned*)&g_Qh[(((size_t)b_ * HH + h) * SS + srow) * DH + d] =
                        pack_h2(vx * SCALE_L2, vy * SCALE_L2);
                } else if (region == 1) {
                    *(unsigned*)&g_Kh[(((size_t)b_ * HH + h) * SS + srow) * DH + d] =
                        pack_h2(vx, vy);
                } else {
                    const size_t base = (((size_t)b_ * HH + h) * DH + d) * SS + srow;
                    g_Vh[base]      = f2h(vx);
                    g_Vh[base + SS] = f2h(vy);
                }
            }
        }
    }
}

// ---- output GEMM: A = g_Oh, W = g_Wh[3], f32 out + bias ------------------
__global__ __launch_bounds__(256, 2) void gemm_o(
    const float* __restrict__ bias, float* __restrict__ outp)
{
    extern __shared__ unsigned short smem_h[];
    unsigned short* Ash = smem_h;
    unsigned short* Bsh = smem_h + 3 * GH_TILE;
    const unsigned abase = (unsigned)__cvta_generic_to_shared(Ash);
    const unsigned bbase = (unsigned)__cvta_generic_to_shared(Bsh);

    const int bm = blockIdx.y * 128;
    const int bn = blockIdx.x * 128;
    const int tid = threadIdx.x;
    const int warp = tid >> 5, lane = tid & 31;
    const int g = lane >> 2, t = lane & 3;
    const int wm0 = (warp >> 1) * 32;
    const int wn0 = (warp & 1) * 64;

    const int q4 = lane >> 3, rr = lane & 7;
    unsigned aoff[2], boff[4];
#pragma unroll
    for (int mi = 0; mi < 2; mi++)
        aoff[mi] = ((unsigned)(wm0 + 16 * mi + ((q4 & 1) << 3) + rr) * GH_STR
                    + ((q4 >> 1) << 3)) * 2;
#pragma unroll
    for (int j = 0; j < 4; j++)
        boff[j] = ((unsigned)(wn0 + 16 * j + ((q4 >> 1) << 3) + rr) * GH_STR
                   + ((q4 & 1) << 3)) * 2;

    const int seg = tid & 3;
    const int row0 = tid >> 2, row1 = row0 + 64;
    const unsigned short* Abase = g_Oh + (size_t)bm * DD;
    const unsigned short* Bw = g_Wh + (size_t)3 * DD * DD;

    auto load_chunk = [&](int kt, int buf) {
        const int k0 = kt * 32 + seg * 8;
        const unsigned ab = abase + (unsigned)buf * GH_TILE * 2;
        const unsigned bb = bbase + (unsigned)buf * GH_TILE * 2;
        cp_async16(ab + (unsigned)row0 * 80 + seg * 16, Abase + (size_t)row0 * DD + k0);
        cp_async16(ab + (unsigned)row1 * 80 + seg * 16, Abase + (size_t)row1 * DD + k0);
        cp_async16(bb + (unsigned)row0 * 80 + seg * 16, Bw + (size_t)(bn + row0) * DD + k0);
        cp_async16(bb + (unsigned)row1 * 80 + seg * 16, Bw + (size_t)(bn + row1) * DD + k0);
        cp_commit();
    };

    float acc[2][8][4];
#pragma unroll
    for (int mi = 0; mi < 2; mi++)
#pragma unroll
        for (int ni = 0; ni < 8; ni++)
#pragma unroll
            for (int q = 0; q < 4; q++) acc[mi][ni][q] = 0.f;

    load_chunk(0, 0);
    load_chunk(1, 1);

    const int NKT = DD / 32;
    for (int kt = 0; kt < NKT; kt++) {
        if (kt + 1 < NKT) { cp_wait<1>(); } else { cp_wait<0>(); }
        __syncthreads();
        if (kt + 2 < NKT) load_chunk(kt + 2, (kt + 2) % 3);

        const int buf = kt % 3;
        const unsigned aB = abase + (unsigned)buf * GH_TILE * 2;
        const unsigned bB = bbase + (unsigned)buf * GH_TILE * 2;
#pragma unroll
        for (int ks = 0; ks < 2; ks++) {
            const unsigned kb = (unsigned)(32 * ks);
            unsigned a[2][4], bt[4][4];
            ldsm_x4(a[0], aB + aoff[0] + kb);
            ldsm_x4(a[1], aB + aoff[1] + kb);
#pragma unroll
            for (int j = 0; j < 4; j++)
                ldsm_x4(bt[j], bB + boff[j] + kb);
#pragma unroll
            for (int mi = 0; mi < 2; mi++)
#pragma unroll
                for (int ni = 0; ni < 8; ni++)
                    mma_f16(acc[mi][ni], a[mi], &bt[ni >> 1][(ni & 1) << 1]);
        }
    }

#pragma unroll
    for (int mi = 0; mi < 2; mi++) {
#pragma unroll
        for (int ni = 0; ni < 8; ni++) {
            const int c = bn + wn0 + 8 * ni + 2 * t;
            const float2 bb = *(const float2*)&bias[c];
#pragma unroll
            for (int hr = 0; hr < 2; hr++) {
                const int r = bm + wm0 + 16 * mi + g + 8 * hr;
                *(float2*)&outp[(size_t)r * DD + c] =
                    make_float2(acc[mi][ni][2 * hr + 0] + bb.x,
                                acc[mi][ni][2 * hr + 1] + bb.y);
            }
        }
    }
}

// ---------------------------------------------------------------------------
// FP16 flash attention (triple-buffered K/V, ldmatrix fragment loads,
// log2-domain softmax):
//  - CTA = 128 q rows of one (b,h), 256 threads (8 warps x 16 rows)
//  - Q fragments register-resident; P stays in registers
// ---------------------------------------------------------------------------
#define AH_STR 72                       // halfs per smem row
#define AH_QSZ (128*AH_STR)
#define AH_CSZ (64*AH_STR)              // one K or Vt chunk
#define AH_SMEM ((AH_QSZ + 6*AH_CSZ)*2) // 73728 bytes

__global__ __launch_bounds__(256, 2) void attn_h()
{
    extern __shared__ unsigned short smh[];
    unsigned short* Qs  = smh;                       // [128][72]
    unsigned short* Ks  = smh + AH_QSZ;              // [3][64][72]
    unsigned short* Vts = smh + AH_QSZ + 3 * AH_CSZ; // [3][64][72]

    const int qb = blockIdx.x;          // 0..15
    const int bh = blockIdx.y;          // 0..63
    const unsigned short* Qg  = g_Qh + (size_t)bh * SS * DH + (size_t)qb * 128 * DH;
    const unsigned short* Kg  = g_Kh + (size_t)bh * SS * DH;
    const unsigned short* Vtg = g_Vh + (size_t)bh * DH * SS;

    const int tid = threadIdx.x;
    const int warp = tid >> 5, lane = tid & 31;
    const int g = lane >> 2, t = lane & 3;
    const int m0 = warp * 16;

    const unsigned qbase = (unsigned)__cvta_generic_to_shared(Qs);
    const unsigned kbase = (unsigned)__cvta_generic_to_shared(Ks);
    const unsigned vbase = (unsigned)__cvta_generic_to_shared(Vts);

    // ldmatrix per-lane offsets
    const int q4 = lane >> 3, rr = lane & 7;
    const unsigned qoff = ((unsigned)(m0 + ((q4 & 1) << 3) + rr) * AH_STR
                           + ((q4 >> 1) << 3)) * 2;
    unsigned noff[4];
#pragma unroll
    for (int j = 0; j < 4; j++)
        noff[j] = ((unsigned)(16 * j + ((q4 >> 1) << 3) + rr) * AH_STR
                   + ((q4 & 1) << 3)) * 2;

    const int seg = tid & 7;            // 16B (8 halfs) column
    const int r0 = tid >> 3, r1 = r0 + 32;

    // Q load (group 0)
#pragma unroll
    for (int p = 0; p < 4; p++) {
        const int row = r0 + 32 * p;
        cp_async16(qbase + (unsigned)row * (AH_STR * 2) + seg * 16,
                   Qg + (size_t)row * DH + seg * 8);
    }
    cp_commit();

    auto load_kv = [&](int kv0, int buf) {
        const unsigned kb = kbase + (unsigned)buf * AH_CSZ * 2;
        const unsigned vb = vbase + (unsigned)buf * AH_CSZ * 2;
        cp_async16(kb + (unsigned)r0 * (AH_STR * 2) + seg * 16,
                   Kg + (size_t)(kv0 + r0) * DH + seg * 8);
        cp_async16(kb + (unsigned)r1 * (AH_STR * 2) + seg * 16,
                   Kg + (size_t)(kv0 + r1) * DH + seg * 8);
        cp_async16(vb + (unsigned)r0 * (AH_STR * 2) + seg * 16,
                   Vtg + (size_t)r0 * SS + kv0 + seg * 8);
        cp_async16(vb + (unsigned)r1 * (AH_STR * 2) + seg * 16,
                   Vtg + (size_t)r1 * SS + kv0 + seg * 8);
        cp_commit();
    };

    load_kv(0, 0);        // group 1
    load_kv(64, 1);       // group 2
    cp_wait<2>();         // Q landed
    __syncthreads();

    // Q fragments -> registers via ldmatrix
    unsigned qf[4][4];
#pragma unroll
    for (int ks = 0; ks < 4; ks++)
        ldsm_x4(qf[ks], qbase + qoff + 32 * ks);

    float o[8][4];
#pragma unroll
    for (int ni = 0; ni < 8; ni++)
#pragma unroll
        for (int q = 0; q < 4; q++) o[ni][q] = 0.f;
    float mi0 = -1e30f, mi1 = -1e30f, li0 = 0.f, li1 = 0.f;

    const int NCH = SS / 64;  // 32
    for (int kt = 0; kt < NCH; kt++) {
        if (kt + 1 < NCH) { cp_wait<1>(); } else { cp_wait<0>(); }
        __syncthreads();
        if (kt + 2 < NCH) load_kv((kt + 2) * 64, (kt + 2) % 3);

        const int buf = kt % 3;
        const unsigned kB = kbase + (unsigned)buf * AH_CSZ * 2;
        const unsigned vB = vbase + (unsigned)buf * AH_CSZ * 2;

        // S = Q K^T : warp 16x64
        float s[8][4];
#pragma unroll
        for (int ni = 0; ni < 8; ni++)
#pragma unroll
            for (int q = 0; q < 4; q++) s[ni][q] = 0.f;

#pragma unroll
        for (int ks = 0; ks < 4; ks++) {
            const unsigned kb = (unsigned)(32 * ks);
            unsigned bt[4][4];
#pragma unroll
            for (int j = 0; j < 4; j++)
                ldsm_x4(bt[j], kB + noff[j] + kb);
#pragma unroll
            for (int ni = 0; ni < 8; ni++)
                mma_f16(s[ni], qf[ks], &bt[ni >> 1][(ni & 1) << 1]);
        }

        // online softmax (log2 domain); P packed straight into A-fragments
        float mx0 = -1e30f, mx1 = -1e30f;
#pragma unroll
        for (int ni = 0; ni < 8; ni++) {
            mx0 = fmaxf(mx0, fmaxf(s[ni][0], s[ni][1]));
            mx1 = fmaxf(mx1, fmaxf(s[ni][2], s[ni][3]));
        }
        mx0 = fmaxf(mx0, __shfl_xor_sync(0xffffffffu, mx0, 1));
        mx0 = fmaxf(mx0, __shfl_xor_sync(0xffffffffu, mx0, 2));
        mx1 = fmaxf(mx1, __shfl_xor_sync(0xffffffffu, mx1, 1));
        mx1 = fmaxf(mx1, __shfl_xor_sync(0xffffffffu, mx1, 2));

        const float mn0 = fmaxf(mi0, mx0), mn1 = fmaxf(mi1, mx1);
        const float corr0 = ex2(mi0 - mn0), corr1 = ex2(mi1 - mn1);
        mi0 = mn0; mi1 = mn1;

        unsigned pa[4][4];
        float rs0 = 0.f, rs1 = 0.f;
#pragma unroll
        for (int ni = 0; ni < 8; ni++) {
            const float p00 = ex2(s[ni][0] - mn0);
            const float p01 = ex2(s[ni][1] - mn0);
            const float p10 = ex2(s[ni][2] - mn1);
            const float p11 = ex2(s[ni][3] - mn1);
            rs0 += p00 + p01;
            rs1 += p10 + p11;
            const int ks = ni >> 1, hi = (ni & 1) << 1;
            pa[ks][hi + 0] = pack_h2(p00, p01);
            pa[ks][hi + 1] = pack_h2(p10, p11);
        }
        rs0 += __shfl_xor_sync(0xffffffffu, rs0, 1);
        rs0 += __shfl_xor_sync(0xffffffffu, rs0, 2);
        rs1 += __shfl_xor_sync(0xffffffffu, rs1, 1);
        rs1 += __shfl_xor_sync(0xffffffffu, rs1, 2);
        li0 = li0 * corr0 + rs0;
        li1 = li1 * corr1 + rs1;
#pragma unroll
        for (int ni = 0; ni < 8; ni++) {
            o[ni][0] *= corr0; o[ni][1] *= corr0;
            o[ni][2] *= corr1; o[ni][3] *= corr1;
        }

        // O += P V : warp 16x64 (B-frags via ldmatrix from V-transposed)
#pragma unroll
        for (int ks = 0; ks < 4; ks++) {
            const unsigned kb = (unsigned)(32 * ks);
            unsigned bt[4][4];
#pragma unroll
            for (int j = 0; j < 4; j++)
                ldsm_x4(bt[j], vB + noff[j] + kb);
#pragma unroll
            for (int ni = 0; ni < 8; ni++)
                mma_f16(o[ni], pa[ks], &bt[ni >> 1][(ni & 1) << 1]);
        }
    }

    // epilogue: normalize, write fp16 g_Oh [B,S,D]
    const int b = bh >> 4, h = bh & 15;
    const float inv0 = 1.f / li0, inv1 = 1.f / li1;
    const int s0 = qb * 128 + m0 + g;
#pragma unroll
    for (int ni = 0; ni < 8; ni++) {
        const int col = h * DH + 8 * ni + 2 * t;
        *(unsigned*)&g_Oh[((size_t)b * SS + s0) * DD + col] =
            pack_h2(o[ni][0] * inv0, o[ni][1] * inv0);
        *(unsigned*)&g_Oh[((size_t)b * SS + s0 + 8) * DD + col] =
            pack_h2(o[ni][2] * inv1, o[ni][3] * inv1);
    }
}

// ---------------------------------------------------------------------------
extern "C" void kernel_launch(void* const* d_in, const int* in_sizes, int n_in,
                              void* d_out, int out_size)
{
    const float* x  = (const float*)d_in[0];
    const float* Wq = (const float*)d_in[1];
    const float* bq = (const float*)d_in[2];
    const float* Wk = (const float*)d_in[3];
    const float* bk = (const float*)d_in[4];
    const float* Wv = (const float*)d_in[5];
    const float* bv = (const float*)d_in[6];
    const float* Wo = (const float*)d_in[7];
    const float* bo = (const float*)d_in[8];
    float* out = (float*)d_out;

    static int configured = 0;
    if (!configured) {
        cudaFuncSetAttribute(gemm_qkv, cudaFuncAttributeMaxDynamicSharedMemorySize, GH_SMEM);
        cudaFuncSetAttribute(gemm_o,   cudaFuncAttributeMaxDynamicSharedMemorySize, GH_SMEM);
        cudaFuncSetAttribute(attn_h,   cudaFuncAttributeMaxDynamicSharedMemorySize, AH_SMEM);
        configured = 1;
    }

    prep<<<8192, 256>>>(x, Wq, Wk, Wv, Wo);
    gemm_qkv<<<dim3(24, 64), 256, GH_SMEM>>>(bq, bk, bv);
    attn_h<<<dim3(SS / 128, BB * HH), 256, AH_SMEM>>>();
    gemm_o<<<dim3(8, 64), 256, GH_SMEM>>>(bo, out);
}